// round 6
// baseline (speedup 1.0000x reference)
#include <cuda_runtime.h>
#include <cuda_bf16.h>
#include <cstdint>
#include <math.h>

#define B_    16
#define N_    4096
#define CIN   256
#define CH_   256
#define DW    512
#define IN_   128

// tcgen05 asm only compiles under an 'a'-suffixed target pass.
#if defined(__CUDA_ARCH_FEAT_SM103_ALL) || defined(__CUDA_ARCH_FEAT_SM100_ALL) || defined(__CUDA_ARCH_FEAT_SM101_ALL)
#define USE_TCGEN05 1
#else
#define USE_TCGEN05 0
#endif

// -------------------- device scratch --------------------
__device__ float g_attw[B_ * DW];
__device__ float g_h[B_ * 2 * DW];   // conv rows n=0 / n=1024 per batch
// 16 pre-swizzled W chunk images of 32KB each (256 rows x 128B, SW128 baked in).
// chunk t = kb*4 + part, part = islo*2 + nh.
// Row perm: w_conv row d (c=d&255, r=d>>8) -> nh=c>>7, local row=(c&127)+r*128.
// In cg2: rank nh holds its chunks; D col = r*256 + c.
__device__ __nv_bfloat16 g_w3[16 * 256 * 64];

// -------------------- PTX helpers --------------------
__device__ __forceinline__ uint32_t smem_u32(const void* p) {
    uint32_t a;
    asm("{ .reg .u64 t; cvta.to.shared.u64 t, %1; cvt.u32.u64 %0, t; }" : "=r"(a) : "l"(p));
    return a;
}
__device__ __forceinline__ uint32_t elect_one() {
    uint32_t pred;
    asm volatile("{\n\t.reg .pred p;\n\telect.sync _|p, 0xFFFFFFFF;\n\tselp.b32 %0, 1, 0, p;\n\t}" : "=r"(pred));
    return pred;
}
#define TCGEN05_ALLOC_CG2(sa, n) \
    asm volatile("tcgen05.alloc.cta_group::2.sync.aligned.shared::cta.b32 [%0], %1;" :: "r"((uint32_t)(sa)), "r"((uint32_t)(n)) : "memory")
#define TCGEN05_DEALLOC_CG2(t, n) \
    asm volatile("tcgen05.dealloc.cta_group::2.sync.aligned.b32 %0, %1;" :: "r"(t), "r"((uint32_t)(n)))
#define TCGEN05_RELINQ_CG2() \
    asm volatile("tcgen05.relinquish_alloc_permit.cta_group::2.sync.aligned;")
#define TCGEN05_COMMIT_MC_CG2(mb) \
    asm volatile("tcgen05.commit.cta_group::2.mbarrier::arrive::one.shared::cluster.multicast::cluster.b64 [%0], %1;" \
        :: "r"((uint32_t)(mb)), "h"((uint16_t)0x3) : "memory")
#define TCGEN05_WAIT_LD() asm volatile("tcgen05.wait::ld.sync.aligned;" ::: "memory")
#define TCGEN05_FENCE_AFTER() asm volatile("tcgen05.fence::after_thread_sync;" ::: "memory")
#define MBARRIER_INIT(mb, cnt) \
    asm volatile("mbarrier.init.shared.b64 [%0], %1;" :: "r"((uint32_t)(mb)), "r"((uint32_t)(cnt)) : "memory")
#define MBARRIER_ARRIVE_CLUSTER(mb, rnk) \
    asm volatile("{\n\t.reg .b32 ra;\n\tmapa.shared::cluster.u32 ra, %0, %1;\n\t" \
        "mbarrier.arrive.shared::cluster.b64 _, [ra];\n\t}" \
        :: "r"((uint32_t)(mb)), "r"((uint32_t)(rnk)) : "memory")
#define MBARRIER_EXPECT_TX(mb, bytes) \
    asm volatile("mbarrier.arrive.expect_tx.shared.b64 _, [%0], %1;" :: "r"((uint32_t)(mb)), "r"((uint32_t)(bytes)) : "memory")
#define MBARRIER_WAIT_PARITY(mb, ph) do { \
    uint32_t _m = (uint32_t)(mb), _p = (uint32_t)(ph), _d; \
    asm volatile("{\n\t.reg .pred p;\n\tmbarrier.try_wait.parity.acquire.cta.shared::cta.b64 p, [%1], %2;\n\tselp.b32 %0, 1, 0, p;\n\t}" \
        : "=r"(_d) : "r"(_m), "r"(_p) : "memory"); \
    if (!_d) { \
        asm volatile("{\n\t.reg .pred P1;\n\tWL_%=:\n\tmbarrier.try_wait.parity.acquire.cta.shared::cta.b64 P1, [%0], %1, 0x989680;\n\t@P1 bra.uni WD_%=;\n\tbra.uni WL_%=;\n\tWD_%=:\n\t}" \
            :: "r"(_m), "r"(_p) : "memory"); \
    } \
} while (0)
#define BULK_G2S(dst, src, bytes, mb) \
    asm volatile("cp.async.bulk.shared::cta.global.mbarrier::complete_tx::bytes [%0], [%1], %2, [%3];" \
        :: "r"((uint32_t)(dst)), "l"(src), "r"((uint32_t)(bytes)), "r"((uint32_t)(mb)) : "memory")
#define CLUSTER_SYNC() do { \
    asm volatile("barrier.cluster.arrive.aligned;" ::: "memory"); \
    asm volatile("barrier.cluster.wait.aligned;" ::: "memory"); \
} while (0)
#define TCGEN05_LD_X32(r, ta) \
    asm volatile("tcgen05.ld.sync.aligned.32x32b.x32.b32 " \
        "{%0,%1,%2,%3,%4,%5,%6,%7,%8,%9,%10,%11,%12,%13,%14,%15," \
        "%16,%17,%18,%19,%20,%21,%22,%23,%24,%25,%26,%27,%28,%29,%30,%31}, [%32];" \
        : "=r"((r)[0]),"=r"((r)[1]),"=r"((r)[2]),"=r"((r)[3]),"=r"((r)[4]),"=r"((r)[5]),"=r"((r)[6]),"=r"((r)[7]), \
          "=r"((r)[8]),"=r"((r)[9]),"=r"((r)[10]),"=r"((r)[11]),"=r"((r)[12]),"=r"((r)[13]),"=r"((r)[14]),"=r"((r)[15]), \
          "=r"((r)[16]),"=r"((r)[17]),"=r"((r)[18]),"=r"((r)[19]),"=r"((r)[20]),"=r"((r)[21]),"=r"((r)[22]),"=r"((r)[23]), \
          "=r"((r)[24]),"=r"((r)[25]),"=r"((r)[26]),"=r"((r)[27]),"=r"((r)[28]),"=r"((r)[29]),"=r"((r)[30]),"=r"((r)[31]) \
        : "r"(ta))

static constexpr uint64_t SMEM_DESC_BASE_SW128 =
    (uint64_t(2) << 61) | (uint64_t(1) << 46) | (uint64_t(64) << 32) | (uint64_t(1) << 16);
#define MAKE_SMEM_DESC(a) (SMEM_DESC_BASE_SW128 | ((uint64_t)((a) >> 4) & 0x3FFF))

#if USE_TCGEN05
// cg2 SS bf16 MMA: D[256,256] += A[256,16] * B[256,16]^T (M split across pair,
// B rows split N/2 per CTA). Leader (rank 0) issues.
__device__ __forceinline__ void mma_f16_ss_cg2(uint32_t d, uint64_t ad, uint64_t bd, uint32_t idesc, bool acc) {
    uint32_t en = acc ? 1u : 0u;
    asm volatile(
        "{\n\t.reg .pred p;\n\tsetp.ne.u32 p, %5, 0;\n\t"
        "tcgen05.mma.cta_group::2.kind::f16 [%0], %1, %2, %3, {%4,%4,%4,%4,%4,%4,%4,%4}, p;\n\t}"
        :: "r"(d), "l"(ad), "l"(bd), "r"(idesc), "r"(0u), "r"(en) : "memory");
}
#endif
// idesc: F32 accum, BF16 x BF16, M=256 (cg2), N=256
static constexpr uint32_t IDESC2 =
    (1u << 4) | (1u << 7) | (1u << 10) | ((256u / 8u) << 17) | ((256u / 16u) << 24);

// fp32 -> bf16 hi/lo split, packed pairs
__device__ __forceinline__ void split4(const float4 v, uint32_t& h01, uint32_t& h23,
                                       uint32_t& l01, uint32_t& l23) {
    __nv_bfloat162 h0 = __floats2bfloat162_rn(v.x, v.y);
    __nv_bfloat162 h1 = __floats2bfloat162_rn(v.z, v.w);
    __nv_bfloat162 l0 = __floats2bfloat162_rn(v.x - __bfloat162float(h0.x),
                                              v.y - __bfloat162float(h0.y));
    __nv_bfloat162 l1 = __floats2bfloat162_rn(v.z - __bfloat162float(h1.x),
                                              v.w - __bfloat162float(h1.y));
    h01 = *(uint32_t*)&h0; h23 = *(uint32_t*)&h1;
    l01 = *(uint32_t*)&l0; l23 = *(uint32_t*)&l1;
}

// ---------------------------------------------------------------------------
// Setup 1: blocks 0..31 = conv rows -> g_h; blocks 32..95 = prep_w.
// ---------------------------------------------------------------------------
__global__ __launch_bounds__(512) void setup1_kernel(
    const float* __restrict__ x,
    const float* __restrict__ w_conv,
    const float* __restrict__ b_conv)
{
    const int tid = threadIdx.x;

    if (blockIdx.x >= 32) {
        const int gi = ((blockIdx.x - 32) * 512 + tid) * 4;
        float4 v = *(const float4*)(w_conv + gi);
        const int d = gi >> 8, k = gi & 255;
        uint32_t h01, h23, l01, l23;
        split4(v, h01, h23, l01, l23);
        const int c = d & 255, r = d >> 8;
        const int nh = c >> 7;
        const int lrow = (c & 127) + (r << 7);
        const int kb = k >> 6, kc = k & 63;
        const uint32_t off = (uint32_t)lrow * 128 + (((uint32_t)kc * 2) ^ ((uint32_t)(lrow & 7) << 4));
        char* basehi = (char*)g_w3 + (size_t)(kb * 4 + nh) * 32768 + off;
        char* baselo = (char*)g_w3 + (size_t)(kb * 4 + 2 + nh) * 32768 + off;
        *(uint2*)basehi = make_uint2(h01, h23);
        *(uint2*)baselo = make_uint2(l01, l23);
        return;
    }

    const int b   = blockIdx.x >> 1;
    const int row = (blockIdx.x & 1) * 1024;
    __shared__ float xs[CIN];
    if (tid < CIN) xs[tid] = x[((size_t)b * N_ + row) * CIN + tid];
    __syncthreads();

    const int d = tid;
    const float4* w = (const float4*)(w_conv + d * CIN);
    float s = 0.f;
    #pragma unroll 8
    for (int k4 = 0; k4 < CIN / 4; k4++) {
        float4 wv = w[k4];
        float4 xv = ((const float4*)xs)[k4];
        s += wv.x * xv.x + wv.y * xv.y + wv.z * xv.z + wv.w * xv.w;
    }
    g_h[(b * 2 + (blockIdx.x & 1)) * DW + d] = fmaxf(s + b_conv[d], 0.f);
}

// ---------------------------------------------------------------------------
// Setup 2: fc chain per batch; attw = sigmoid(pair difference), b_fc2 cancels.
// ---------------------------------------------------------------------------
__global__ __launch_bounds__(256) void setup2_kernel(
    const float* __restrict__ w_fc1,
    const float* __restrict__ b_fc1,
    const float* __restrict__ w_fc2)
{
    const int b   = blockIdx.x;
    const int tid = threadIdx.x;
    __shared__ float gap0[CH_], gap1[CH_];
    __shared__ float g0[IN_], g1[IN_], gd[IN_];

    const float* h0 = g_h + (b * 2 + 0) * DW;
    const float* h1 = g_h + (b * 2 + 1) * DW;
    gap0[tid] = h0[tid] + h0[tid + CH_];
    gap1[tid] = h1[tid] + h1[tid + CH_];
    __syncthreads();

    {
        const int i = tid & 127;
        const float* gp = (tid < 128) ? gap0 : gap1;
        const float4* w = (const float4*)(w_fc1 + i * CH_);
        float s = 0.f;
        #pragma unroll 8
        for (int k4 = 0; k4 < CH_ / 4; k4++) {
            float4 wv = w[k4];
            float4 gv = ((const float4*)gp)[k4];
            s += wv.x * gv.x + wv.y * gv.y + wv.z * gv.z + wv.w * gv.w;
        }
        s = fmaxf(s + b_fc1[i], 0.f);
        if (tid < 128) g0[i] = s; else g1[i] = s;
    }
    __syncthreads();
    if (tid < IN_) gd[tid] = g0[tid] - g1[tid];
    __syncthreads();

    #pragma unroll
    for (int dd = 0; dd < 2; dd++) {
        const int d = tid + dd * 256;
        const float4* w = (const float4*)(w_fc2 + d * IN_);
        float s = 0.f;
        #pragma unroll 8
        for (int k4 = 0; k4 < IN_ / 4; k4++) {
            float4 wv = w[k4];
            float4 gv = ((const float4*)gd)[k4];
            s += wv.x * gv.x + wv.y * gv.y + wv.z * gv.z + wv.w * gv.w;
        }
        g_attw[b * DW + d] = 1.f / (1.f + expf(-s));
    }
}

// ---------------------------------------------------------------------------
// GEMM: cg2 (cluster-2) tcgen05, D[256,512] per pair, each CTA owns 128 rows
// and its N-half of W (halves L2->SM W traffic vs cg1).
// Warp0: rank0 = MMA issue, rank1 = relay (forwards W-ready to leader).
// Warp1: per-CTA W producer (bulk copies own 8 chunks).
// Warps 2-15: A loaders (LDG fp32 + hi/lo split + swizzled STS).
// ---------------------------------------------------------------------------
#define A_OFF   1024
#define W_OFF   (1024 + 65536)
#define SMEM_TOTAL (1024 + 65536 + 131072)

__global__ __launch_bounds__(512, 1) __cluster_dims__(2, 1, 1)
void gemm_kernel(const float* __restrict__ x,
                 const float* __restrict__ w_conv,
                 const float* __restrict__ b_conv,
                 float* __restrict__ out)
{
    extern __shared__ __align__(1024) char smem[];
    const int tid = threadIdx.x;
    const int m0  = blockIdx.x * 128;
    const int bb  = m0 >> 12;
    const int n0  = m0 & (N_ - 1);

#if USE_TCGEN05
    const uint32_t sb = smem_u32(smem);
    const int wid  = tid >> 5, lid = tid & 31;
    const int rank = blockIdx.x & 1;

    #define WFH(q) (sb + 8  + (q) * 8)
    #define WFL(q) (sb + 24 + (q) * 8)
    #define PFH(q) (sb + 40 + (q) * 8)
    #define PFL(q) (sb + 56 + (q) * 8)
    #define AFB(q) (sb + 72 + (q) * 8)
    #define ARB(q) (sb + 88 + (q) * 8)
    const uint32_t MDN = sb + 104;

    if (wid == 0) TCGEN05_ALLOC_CG2(sb, 512);
    if (tid == 0) {
        #pragma unroll
        for (int q = 0; q < 2; q++) {
            MBARRIER_INIT(WFH(q), 1); MBARRIER_INIT(WFL(q), 1);
            MBARRIER_INIT(PFH(q), 1); MBARRIER_INIT(PFL(q), 1);
            MBARRIER_INIT(AFB(q), 896);
            MBARRIER_INIT(ARB(q), 1);
        }
        MBARRIER_INIT(MDN, 1);
    }
    __syncthreads();
    uint32_t tmem;
    asm volatile("ld.shared.b32 %0, [%1];" : "=r"(tmem) : "r"(sb));
    CLUSTER_SYNC();   // barriers visible cluster-wide before remote arrives

    if (wid == 0) {
        if (rank == 0) {
            // ---------------- MMA warp (leader) ----------------
            if (elect_one()) {
                int afph[2] = {0, 0};
                for (int kb = 0; kb < 4; kb++) {
                    const int q = kb & 1, rph = (kb >> 1) & 1;
                    MBARRIER_WAIT_PARITY(AFB(q), afph[q]); afph[q] ^= 1;
                    const uint32_t ab = sb + A_OFF + q * 32768;
                    const uint64_t ahi = MAKE_SMEM_DESC(ab);
                    const uint64_t alo = MAKE_SMEM_DESC(ab + 16384);
                    const uint64_t whi = MAKE_SMEM_DESC(sb + W_OFF + q * 65536);
                    const uint64_t wlo = MAKE_SMEM_DESC(sb + W_OFF + q * 65536 + 32768);

                    MBARRIER_WAIT_PARITY(WFH(q), rph);   // own hi chunk landed
                    MBARRIER_WAIT_PARITY(PFH(q), rph);   // peer hi chunk landed
                    #pragma unroll
                    for (int k = 0; k < 4; k++) {
                        const bool acc = !(kb == 0 && k == 0);
                        mma_f16_ss_cg2(tmem,       ahi + k * 2, whi + k * 2,        IDESC2, acc);
                        mma_f16_ss_cg2(tmem + 256, ahi + k * 2, whi + 1024 + k * 2, IDESC2, acc);
                    }
                    #pragma unroll
                    for (int k = 0; k < 4; k++) {
                        mma_f16_ss_cg2(tmem,       alo + k * 2, whi + k * 2,        IDESC2, true);
                        mma_f16_ss_cg2(tmem + 256, alo + k * 2, whi + 1024 + k * 2, IDESC2, true);
                    }
                    MBARRIER_WAIT_PARITY(WFL(q), rph);
                    MBARRIER_WAIT_PARITY(PFL(q), rph);
                    #pragma unroll
                    for (int k = 0; k < 4; k++) {
                        mma_f16_ss_cg2(tmem,       ahi + k * 2, wlo + k * 2,        IDESC2, true);
                        mma_f16_ss_cg2(tmem + 256, ahi + k * 2, wlo + 1024 + k * 2, IDESC2, true);
                    }
                    TCGEN05_COMMIT_MC_CG2(ARB(q));   // buffers of parity q reusable (both CTAs)
                }
                TCGEN05_COMMIT_MC_CG2(MDN);
            }
        } else {
            // ---------------- relay (rank 1): forward W-ready to leader -------
            if (elect_one()) {
                for (int kb = 0; kb < 4; kb++) {
                    const int q = kb & 1, rph = (kb >> 1) & 1;
                    MBARRIER_WAIT_PARITY(WFH(q), rph);
                    MBARRIER_ARRIVE_CLUSTER(PFH(q), 0);
                    MBARRIER_WAIT_PARITY(WFL(q), rph);
                    MBARRIER_ARRIVE_CLUSTER(PFL(q), 0);
                }
            }
        }
    } else if (wid == 1) {
        // ---------------- W producer: own 8 chunks (hi+lo per kb) ----------
        if (elect_one()) {
            const char* wsrc = (const char*)g_w3;
            int arph[2] = {0, 0};
            for (int kb = 0; kb < 4; kb++) {
                const int q = kb & 1;
                if (kb >= 2) { MBARRIER_WAIT_PARITY(ARB(q), arph[q]); arph[q] ^= 1; }
                MBARRIER_EXPECT_TX(WFH(q), 32768);
                BULK_G2S(sb + W_OFF + q * 65536, wsrc + (size_t)(kb * 4 + rank) * 32768, 32768, WFH(q));
                MBARRIER_EXPECT_TX(WFL(q), 32768);
                BULK_G2S(sb + W_OFF + q * 65536 + 32768, wsrc + (size_t)(kb * 4 + 2 + rank) * 32768, 32768, WFL(q));
            }
        }
    } else {
        // ---------------- A loaders (448 threads, own 128 rows) ------------
        const int lt = tid - 64;
        int frph[2] = {0, 0};
        for (int kb = 0; kb < 4; kb++) {
            const int q = kb & 1;
            if (kb >= 2) { MBARRIER_WAIT_PARITY(ARB(q), frph[q]); frph[q] ^= 1; }
            const uint32_t ab = sb + A_OFF + q * 32768;
            for (int f = lt; f < 2048; f += 448) {
                const int r = f >> 4, qq = f & 15;
                const float4 v = *(const float4*)&x[(size_t)(m0 + r) * 256 + kb * 64 + qq * 4];
                uint32_t h01, h23, l01, l23;
                split4(v, h01, h23, l01, l23);
                const uint32_t off = (uint32_t)r * 128 + (((uint32_t)qq * 8) ^ ((uint32_t)(r & 7) << 4));
                asm volatile("st.shared.v2.b32 [%0], {%1,%2};" :: "r"(ab + off), "r"(h01), "r"(h23) : "memory");
                asm volatile("st.shared.v2.b32 [%0], {%1,%2};" :: "r"(ab + 16384 + off), "r"(l01), "r"(l23) : "memory");
            }
            asm volatile("fence.proxy.async.shared::cta;" ::: "memory");
            MBARRIER_ARRIVE_CLUSTER(AFB(q), 0);   // arrive leader's A-full barrier
        }
    }

    // ---------------- epilogue (both CTAs, own 128 rows x 512 cols) --------
    // D col layout: col = radix*256 + channel.
    MBARRIER_WAIT_PARITY(MDN, 0);
    TCGEN05_FENCE_AFTER();

    if (wid < 8) {
        const int half = wid >> 2;             // channels half*128 .. +127
        const int m    = (wid & 3) * 32 + lid;
        const int n    = n0 + m;
        float* __restrict__ orow = out + ((size_t)n * B_ + bb) * CH_;
        const float* __restrict__ aw = g_attw + bb * DW;
        #pragma unroll 1
        for (int cc = 0; cc < 4; cc++) {
            uint32_t hr0[32], hr1[32];
            TCGEN05_LD_X32(hr0, tmem + half * 128 + cc * 32);          // radix 0
            TCGEN05_LD_X32(hr1, tmem + 256 + half * 128 + cc * 32);    // radix 1
            TCGEN05_WAIT_LD();
            #pragma unroll
            for (int q = 0; q < 8; q++) {
                const int ch = half * 128 + cc * 32 + q * 4;
                float4 b0 = *(const float4*)&b_conv[ch];
                float4 b1 = *(const float4*)&b_conv[256 + ch];
                float4 a0 = *(const float4*)&aw[ch];
                float4 a1 = *(const float4*)&aw[256 + ch];
                float4 o;
                o.x = a0.x * fmaxf(__uint_as_float(hr0[q*4+0]) + b0.x, 0.f)
                    + a1.x * fmaxf(__uint_as_float(hr1[q*4+0]) + b1.x, 0.f);
                o.y = a0.y * fmaxf(__uint_as_float(hr0[q*4+1]) + b0.y, 0.f)
                    + a1.y * fmaxf(__uint_as_float(hr1[q*4+1]) + b1.y, 0.f);
                o.z = a0.z * fmaxf(__uint_as_float(hr0[q*4+2]) + b0.z, 0.f)
                    + a1.z * fmaxf(__uint_as_float(hr1[q*4+2]) + b1.z, 0.f);
                o.w = a0.w * fmaxf(__uint_as_float(hr0[q*4+3]) + b0.w, 0.f)
                    + a1.w * fmaxf(__uint_as_float(hr1[q*4+3]) + b1.w, 0.f);
                *(float4*)(orow + ch) = o;
            }
        }
    }
    __syncthreads();
    if (wid == 0) { TCGEN05_RELINQ_CG2(); TCGEN05_DEALLOC_CG2(tmem, 512); }
    CLUSTER_SYNC();

#else  // ------------------- fp32 FFMA fallback (plain sm_103) --------------
    float (*As)[64]  = (float(*)[64])smem;
    float (*Bs)[516] = (float(*)[516])(smem + 16 * 64 * 4);

    const int trow = tid >> 6;
    const int tcol = tid & 63;
    const int aM = tid >> 2, aK = (tid & 3) << 2;
    const int bD = tid >> 2, bK = (tid & 3) << 2;

    for (int sub = 0; sub < 2; sub++) {
        const int ms = m0 + sub * 64;
        float acc[8][8];
        #pragma unroll
        for (int i = 0; i < 8; i++)
            #pragma unroll
            for (int jj = 0; jj < 8; jj++) acc[i][jj] = 0.f;

        float4 aReg = make_float4(0.f, 0.f, 0.f, 0.f);
        float4 bReg[4];
        if (tid < 256)
            aReg = *(const float4*)&x[(size_t)(ms + aM) * CIN + aK];
        #pragma unroll
        for (int p = 0; p < 4; p++)
            bReg[p] = *(const float4*)&w_conv[(size_t)(bD + p * 128) * CIN + bK];

        for (int ks = 0; ks < CIN; ks += 16) {
            __syncthreads();
            if (tid < 256) {
                As[aK + 0][aM] = aReg.x; As[aK + 1][aM] = aReg.y;
                As[aK + 2][aM] = aReg.z; As[aK + 3][aM] = aReg.w;
            }
            #pragma unroll
            for (int p = 0; p < 4; p++) {
                const int d = bD + p * 128;
                Bs[bK + 0][d] = bReg[p].x; Bs[bK + 1][d] = bReg[p].y;
                Bs[bK + 2][d] = bReg[p].z; Bs[bK + 3][d] = bReg[p].w;
            }
            __syncthreads();
            if (ks + 16 < CIN) {
                const int kn = ks + 16;
                if (tid < 256)
                    aReg = *(const float4*)&x[(size_t)(ms + aM) * CIN + kn + aK];
                #pragma unroll
                for (int p = 0; p < 4; p++)
                    bReg[p] = *(const float4*)&w_conv[(size_t)(bD + p * 128) * CIN + kn + bK];
            }
            #pragma unroll
            for (int k = 0; k < 16; k++) {
                float a[8], bf[8];
                *(float4*)&a[0]  = *(const float4*)&As[k][trow * 8];
                *(float4*)&a[4]  = *(const float4*)&As[k][trow * 8 + 4];
                *(float4*)&bf[0] = *(const float4*)&Bs[k][tcol * 4];
                *(float4*)&bf[4] = *(const float4*)&Bs[k][tcol * 4 + 256];
                #pragma unroll
                for (int i = 0; i < 8; i++)
                    #pragma unroll
                    for (int jj = 0; jj < 8; jj++)
                        acc[i][jj] += a[i] * bf[jj];
            }
        }
        __syncthreads();

        const int cbase = tcol * 4;
        float a0[4], a1[4], bias0[4], bias1[4];
        #pragma unroll
        for (int jj = 0; jj < 4; jj++) {
            a0[jj]    = g_attw[bb * DW + cbase + jj];
            a1[jj]    = g_attw[bb * DW + 256 + cbase + jj];
            bias0[jj] = b_conv[cbase + jj];
            bias1[jj] = b_conv[256 + cbase + jj];
        }
        #pragma unroll
        for (int i = 0; i < 8; i++) {
            const int n = n0 + sub * 64 + trow * 8 + i;
            float4 o;
            o.x = a0[0] * fmaxf(acc[i][0] + bias0[0], 0.f) + a1[0] * fmaxf(acc[i][4] + bias1[0], 0.f);
            o.y = a0[1] * fmaxf(acc[i][1] + bias0[1], 0.f) + a1[1] * fmaxf(acc[i][5] + bias1[1], 0.f);
            o.z = a0[2] * fmaxf(acc[i][2] + bias0[2], 0.f) + a1[2] * fmaxf(acc[i][6] + bias1[2], 0.f);
            o.w = a0[3] * fmaxf(acc[i][3] + bias0[3], 0.f) + a1[3] * fmaxf(acc[i][7] + bias1[3], 0.f);
            *(float4*)&out[((size_t)n * B_ + bb) * CH_ + cbase] = o;
        }
    }
#endif
}

extern "C" void kernel_launch(void* const* d_in, const int* in_sizes, int n_in,
                              void* d_out, int out_size) {
    const float* x      = (const float*)d_in[0];
    const float* w_conv = (const float*)d_in[1];
    const float* b_conv = (const float*)d_in[2];
    const float* w_fc1  = (const float*)d_in[3];
    const float* b_fc1  = (const float*)d_in[4];
    const float* w_fc2  = (const float*)d_in[5];
    // d_in[6] = b_fc2: cancels in the softmax-pair difference, unused.
    float* out = (float*)d_out;

    cudaFuncSetAttribute(gemm_kernel, cudaFuncAttributeMaxDynamicSharedMemorySize, SMEM_TOTAL);

    setup1_kernel<<<96, 512>>>(x, w_conv, b_conv);
    setup2_kernel<<<B_, 256>>>(w_fc1, b_fc1, w_fc2);
    gemm_kernel<<<(B_ * N_) / 128, 512, SMEM_TOTAL>>>(x, w_conv, b_conv, out);
}

// round 7
// speedup vs baseline: 1.0995x; 1.0995x over previous
#include <cuda_runtime.h>
#include <cuda_bf16.h>
#include <cstdint>
#include <math.h>

#define B_    16
#define N_    4096
#define CIN   256
#define CH_   256
#define DW    512
#define IN_   128
#define NTILES_TOTAL 512   // 65536 rows / 128

// tcgen05 asm only compiles under an 'a'-suffixed target pass.
#if defined(__CUDA_ARCH_FEAT_SM103_ALL) || defined(__CUDA_ARCH_FEAT_SM100_ALL) || defined(__CUDA_ARCH_FEAT_SM101_ALL)
#define USE_TCGEN05 1
#else
#define USE_TCGEN05 0
#endif

// -------------------- device scratch --------------------
__device__ float g_attw[B_ * DW];
__device__ float g_h[B_ * 2 * DW];
// 16 pre-swizzled W chunk images of 32KB each (256 rows x 128B, SW128 baked in).
// chunk j = kb*4 + part, part = islo*2 + nh.
// Row perm: w_conv row d (c=d&255, r=d>>8) -> nh=c>>7, local row=(c&127)+r*128.
// D col = nh*256 + (c&127) + r*128.
__device__ __nv_bfloat16 g_w3[16 * 256 * 64];

// -------------------- PTX helpers --------------------
__device__ __forceinline__ uint32_t smem_u32(const void* p) {
    uint32_t a;
    asm("{ .reg .u64 t; cvta.to.shared.u64 t, %1; cvt.u32.u64 %0, t; }" : "=r"(a) : "l"(p));
    return a;
}
__device__ __forceinline__ uint32_t elect_one() {
    uint32_t pred;
    asm volatile("{\n\t.reg .pred p;\n\telect.sync _|p, 0xFFFFFFFF;\n\tselp.b32 %0, 1, 0, p;\n\t}" : "=r"(pred));
    return pred;
}
#define TCGEN05_ALLOC(sa, n) \
    asm volatile("tcgen05.alloc.cta_group::1.sync.aligned.shared::cta.b32 [%0], %1;" :: "r"((uint32_t)(sa)), "r"((uint32_t)(n)) : "memory")
#define TCGEN05_DEALLOC(t, n) \
    asm volatile("tcgen05.dealloc.cta_group::1.sync.aligned.b32 %0, %1;" :: "r"(t), "r"((uint32_t)(n)))
#define TCGEN05_RELINQ() \
    asm volatile("tcgen05.relinquish_alloc_permit.cta_group::1.sync.aligned;")
#define TCGEN05_COMMIT(mb) \
    asm volatile("tcgen05.commit.cta_group::1.mbarrier::arrive::one.shared::cluster.b64 [%0];" :: "r"((uint32_t)(mb)) : "memory")
#define TCGEN05_WAIT_LD() asm volatile("tcgen05.wait::ld.sync.aligned;" ::: "memory")
#define TCGEN05_FENCE_AFTER() asm volatile("tcgen05.fence::after_thread_sync;" ::: "memory")
#define MBARRIER_INIT(mb, cnt) \
    asm volatile("mbarrier.init.shared.b64 [%0], %1;" :: "r"((uint32_t)(mb)), "r"((uint32_t)(cnt)) : "memory")
#define MBARRIER_ARRIVE(mb) \
    asm volatile("mbarrier.arrive.shared.b64 _, [%0];" :: "r"((uint32_t)(mb)) : "memory")
#define MBARRIER_EXPECT_TX(mb, bytes) \
    asm volatile("mbarrier.arrive.expect_tx.shared.b64 _, [%0], %1;" :: "r"((uint32_t)(mb)), "r"((uint32_t)(bytes)) : "memory")
#define MBARRIER_WAIT_PARITY(mb, ph) do { \
    uint32_t _m = (uint32_t)(mb), _p = (uint32_t)(ph), _d; \
    asm volatile("{\n\t.reg .pred p;\n\tmbarrier.try_wait.parity.acquire.cta.shared::cta.b64 p, [%1], %2;\n\tselp.b32 %0, 1, 0, p;\n\t}" \
        : "=r"(_d) : "r"(_m), "r"(_p) : "memory"); \
    if (!_d) { \
        asm volatile("{\n\t.reg .pred P1;\n\tWL_%=:\n\tmbarrier.try_wait.parity.acquire.cta.shared::cta.b64 P1, [%0], %1, 0x989680;\n\t@P1 bra.uni WD_%=;\n\tbra.uni WL_%=;\n\tWD_%=:\n\t}" \
            :: "r"(_m), "r"(_p) : "memory"); \
    } \
} while (0)
#define BULK_G2S(dst, src, bytes, mb) \
    asm volatile("cp.async.bulk.shared::cta.global.mbarrier::complete_tx::bytes [%0], [%1], %2, [%3];" \
        :: "r"((uint32_t)(dst)), "l"(src), "r"((uint32_t)(bytes)), "r"((uint32_t)(mb)) : "memory")
#define TCGEN05_LD_X32(r, ta) \
    asm volatile("tcgen05.ld.sync.aligned.32x32b.x32.b32 " \
        "{%0,%1,%2,%3,%4,%5,%6,%7,%8,%9,%10,%11,%12,%13,%14,%15," \
        "%16,%17,%18,%19,%20,%21,%22,%23,%24,%25,%26,%27,%28,%29,%30,%31}, [%32];" \
        : "=r"((r)[0]),"=r"((r)[1]),"=r"((r)[2]),"=r"((r)[3]),"=r"((r)[4]),"=r"((r)[5]),"=r"((r)[6]),"=r"((r)[7]), \
          "=r"((r)[8]),"=r"((r)[9]),"=r"((r)[10]),"=r"((r)[11]),"=r"((r)[12]),"=r"((r)[13]),"=r"((r)[14]),"=r"((r)[15]), \
          "=r"((r)[16]),"=r"((r)[17]),"=r"((r)[18]),"=r"((r)[19]),"=r"((r)[20]),"=r"((r)[21]),"=r"((r)[22]),"=r"((r)[23]), \
          "=r"((r)[24]),"=r"((r)[25]),"=r"((r)[26]),"=r"((r)[27]),"=r"((r)[28]),"=r"((r)[29]),"=r"((r)[30]),"=r"((r)[31]) \
        : "r"(ta))

static constexpr uint64_t SMEM_DESC_BASE_SW128 =
    (uint64_t(2) << 61) | (uint64_t(1) << 46) | (uint64_t(64) << 32) | (uint64_t(1) << 16);
#define MAKE_SMEM_DESC(a) (SMEM_DESC_BASE_SW128 | ((uint64_t)((a) >> 4) & 0x3FFF))

#if USE_TCGEN05
// SS-mode cg1 bf16 MMA: D[128,256] += A[128,16] * B[256,16]^T
__device__ __forceinline__ void mma_f16_ss(uint32_t d, uint64_t ad, uint64_t bd, uint32_t idesc, bool acc) {
    uint32_t en = acc ? 1u : 0u;
    asm volatile(
        "{\n\t.reg .pred p;\n\tsetp.ne.u32 p, %5, 0;\n\t"
        "tcgen05.mma.cta_group::1.kind::f16 [%0], %1, %2, %3, {%4, %4, %4, %4}, p;\n\t}"
        :: "r"(d), "l"(ad), "l"(bd), "r"(idesc), "r"(0u), "r"(en) : "memory");
}
#endif
// idesc: F32 accum, BF16 x BF16, M=128, N=256
static constexpr uint32_t IDESC =
    (1u << 4) | (1u << 7) | (1u << 10) | ((256u / 8u) << 17) | ((128u / 16u) << 24);

// fp32 -> bf16 hi/lo split, packed pairs
__device__ __forceinline__ void split4(const float4 v, uint32_t& h01, uint32_t& h23,
                                       uint32_t& l01, uint32_t& l23) {
    __nv_bfloat162 h0 = __floats2bfloat162_rn(v.x, v.y);
    __nv_bfloat162 h1 = __floats2bfloat162_rn(v.z, v.w);
    __nv_bfloat162 l0 = __floats2bfloat162_rn(v.x - __bfloat162float(h0.x),
                                              v.y - __bfloat162float(h0.y));
    __nv_bfloat162 l1 = __floats2bfloat162_rn(v.z - __bfloat162float(h1.x),
                                              v.w - __bfloat162float(h1.y));
    h01 = *(uint32_t*)&h0; h23 = *(uint32_t*)&h1;
    l01 = *(uint32_t*)&l0; l23 = *(uint32_t*)&l1;
}

// ---------------------------------------------------------------------------
// Setup 1: blocks 0..63 = conv rows (K-split-2 per dot); 64..127 = prep_w.
// ---------------------------------------------------------------------------
__global__ __launch_bounds__(512) void setup1_kernel(
    const float* __restrict__ x,
    const float* __restrict__ w_conv,
    const float* __restrict__ b_conv)
{
    const int tid = threadIdx.x;

    if (blockIdx.x >= 64) {
        // ---- prep_w: 64 blocks x 512 threads x 4 floats ----
        const int gi = ((blockIdx.x - 64) * 512 + tid) * 4;
        float4 v = *(const float4*)(w_conv + gi);
        const int d = gi >> 8, k = gi & 255;
        uint32_t h01, h23, l01, l23;
        split4(v, h01, h23, l01, l23);
        const int c = d & 255, r = d >> 8;
        const int nh = c >> 7;
        const int lrow = (c & 127) + (r << 7);
        const int kb = k >> 6, kc = k & 63;
        const uint32_t off = (uint32_t)lrow * 128 + (((uint32_t)kc * 2) ^ ((uint32_t)(lrow & 7) << 4));
        char* basehi = (char*)g_w3 + (size_t)(kb * 4 + nh) * 32768 + off;
        char* baselo = (char*)g_w3 + (size_t)(kb * 4 + 2 + nh) * 32768 + off;
        *(uint2*)basehi = make_uint2(h01, h23);
        *(uint2*)baselo = make_uint2(l01, l23);
        return;
    }

    // ---- conv rows: blk = (b<<2) | (rowsel<<1) | dhalf ----
    const int b      = blockIdx.x >> 2;
    const int rowsel = (blockIdx.x >> 1) & 1;
    const int dhalf  = blockIdx.x & 1;
    const int row    = rowsel * 1024;

    __shared__ float xs[CIN];
    __shared__ float psum[512];
    if (tid < CIN) xs[tid] = x[((size_t)b * N_ + row) * CIN + tid];
    __syncthreads();

    const int dl = tid >> 1;           // 0..255
    const int kh = tid & 1;            // K half
    const int d  = dhalf * 256 + dl;
    const float4* w = (const float4*)(w_conv + d * CIN + kh * 128);
    const float4* xv = (const float4*)(xs + kh * 128);
    float s = 0.f;
    #pragma unroll 8
    for (int k4 = 0; k4 < 32; k4++) {
        float4 wv = w[k4];
        float4 x4 = xv[k4];
        s += wv.x * x4.x + wv.y * x4.y + wv.z * x4.z + wv.w * x4.w;
    }
    psum[tid] = s;
    __syncthreads();
    if (kh == 0) {
        float t = psum[tid] + psum[tid + 1];
        g_h[(b * 2 + rowsel) * DW + d] = fmaxf(t + b_conv[d], 0.f);
    }
}

// ---------------------------------------------------------------------------
// Setup 2: fc chain per batch; attw = sigmoid(pair difference), b_fc2 cancels.
// ---------------------------------------------------------------------------
__global__ __launch_bounds__(256) void setup2_kernel(
    const float* __restrict__ w_fc1,
    const float* __restrict__ b_fc1,
    const float* __restrict__ w_fc2)
{
    const int b   = blockIdx.x;
    const int tid = threadIdx.x;
    __shared__ float gap0[CH_], gap1[CH_];
    __shared__ float g0[IN_], g1[IN_], gd[IN_];

    const float* h0 = g_h + (b * 2 + 0) * DW;
    const float* h1 = g_h + (b * 2 + 1) * DW;
    gap0[tid] = h0[tid] + h0[tid + CH_];
    gap1[tid] = h1[tid] + h1[tid + CH_];
    __syncthreads();

    {
        const int i = tid & 127;
        const float* gp = (tid < 128) ? gap0 : gap1;
        const float4* w = (const float4*)(w_fc1 + i * CH_);
        float s = 0.f;
        #pragma unroll 8
        for (int k4 = 0; k4 < CH_ / 4; k4++) {
            float4 wv = w[k4];
            float4 gv = ((const float4*)gp)[k4];
            s += wv.x * gv.x + wv.y * gv.y + wv.z * gv.z + wv.w * gv.w;
        }
        s = fmaxf(s + b_fc1[i], 0.f);
        if (tid < 128) g0[i] = s; else g1[i] = s;
    }
    __syncthreads();
    if (tid < IN_) gd[tid] = g0[tid] - g1[tid];
    __syncthreads();

    #pragma unroll
    for (int dd = 0; dd < 2; dd++) {
        const int d = tid + dd * 256;
        const float4* w = (const float4*)(w_fc2 + d * IN_);
        float s = 0.f;
        #pragma unroll 8
        for (int k4 = 0; k4 < IN_ / 4; k4++) {
            float4 wv = w[k4];
            float4 gv = ((const float4*)gd)[k4];
            s += wv.x * gv.x + wv.y * gv.y + wv.z * gv.z + wv.w * gv.w;
        }
        g_attw[b * DW + d] = 1.f / (1.f + expf(-s));
    }
}

// ---------------------------------------------------------------------------
// GEMM: PERSISTENT cg1 tcgen05. 148 CTAs; CTA processes tiles bid+148*i.
// Per tile: M=128 rows, N=512, K = 3 bf16 products over 4 kb of 64 fp32 cols.
// Pipelines (A 2-stage, W 4-stage) run continuously across tiles.
// Warp 0 = MMA, warp 1 = W producer, warps 2-15 = A loaders;
// warps 2-9 additionally do the TMEM epilogue (EPI barrier gates next tile).
// ---------------------------------------------------------------------------
#define A_OFF   1024
#define W_OFF   (1024 + 65536)
#define SMEM_TOTAL (1024 + 65536 + 131072)
#define GRID_GEMM 148

__global__ __launch_bounds__(512, 1)
void gemm_kernel(const float* __restrict__ x,
                 const float* __restrict__ w_conv,
                 const float* __restrict__ b_conv,
                 float* __restrict__ out)
{
    extern __shared__ __align__(1024) char smem[];
    const int tid = threadIdx.x;

#if USE_TCGEN05
    const uint32_t sb = smem_u32(smem);
    const int wid = tid >> 5, lid = tid & 31;
    const int bid = blockIdx.x;
    const int ntiles = (NTILES_TOTAL - bid + GRID_GEMM - 1) / GRID_GEMM;

    #define WF(s) (sb + 8  + (s) * 8)
    #define WE(s) (sb + 40 + (s) * 8)
    #define AF(q) (sb + 72 + (q) * 8)
    #define AR(q) (sb + 88 + (q) * 8)
    const uint32_t MDN = sb + 104;
    const uint32_t EPI = sb + 112;

    if (wid == 0) TCGEN05_ALLOC(sb, 512);
    if (tid == 0) {
        #pragma unroll
        for (int s = 0; s < 4; s++) { MBARRIER_INIT(WF(s), 1); MBARRIER_INIT(WE(s), 1); }
        MBARRIER_INIT(AF(0), 448); MBARRIER_INIT(AF(1), 448);
        MBARRIER_INIT(AR(0), 1);   MBARRIER_INIT(AR(1), 1);
        MBARRIER_INIT(MDN, 1);     MBARRIER_INIT(EPI, 256);
    }
    __syncthreads();
    uint32_t tmem;
    asm volatile("ld.shared.b32 %0, [%1];" : "=r"(tmem) : "r"(sb));

    if (wid == 0) {
        // ================= MMA warp =================
        if (elect_one()) {
            int afph[2] = {0, 0};
            for (int tt = 0; tt < ntiles; tt++) {
                if (tt > 0) MBARRIER_WAIT_PARITY(EPI, (tt - 1) & 1);  // TMEM free
                #pragma unroll 1
                for (int kb = 0; kb < 4; kb++) {
                    const int c = tt * 4 + kb;       // global A-chunk counter
                    const int q = c & 1;
                    MBARRIER_WAIT_PARITY(AF(q), afph[q]); afph[q] ^= 1;
                    const uint32_t ab = sb + A_OFF + q * 32768;
                    const uint64_t ahi = MAKE_SMEM_DESC(ab);
                    const uint64_t alo = MAKE_SMEM_DESC(ab + 16384);
                    #pragma unroll
                    for (int part = 0; part < 4; part++) {
                        MBARRIER_WAIT_PARITY(WF(part), c & 1);
                        const uint64_t wd = MAKE_SMEM_DESC(sb + W_OFF + part * 32768);
                        const uint32_t dst = tmem + (part & 1) * 256;
                        if (part < 2) {
                            #pragma unroll
                            for (int k = 0; k < 4; k++)
                                mma_f16_ss(dst, ahi + k * 2, wd + k * 2, IDESC, !(kb == 0 && k == 0));
                            #pragma unroll
                            for (int k = 0; k < 4; k++)
                                mma_f16_ss(dst, alo + k * 2, wd + k * 2, IDESC, true);
                        } else {
                            #pragma unroll
                            for (int k = 0; k < 4; k++)
                                mma_f16_ss(dst, ahi + k * 2, wd + k * 2, IDESC, true);
                        }
                        TCGEN05_COMMIT(WE(part));
                    }
                    TCGEN05_COMMIT(AR(q));
                }
                TCGEN05_COMMIT(MDN);
            }
        }
    } else if (wid == 1) {
        // ================= W producer: continuous 4-stage ring =================
        if (elect_one()) {
            const char* wsrc = (const char*)g_w3;
            int weph[4] = {0, 0, 0, 0};
            const int nwc = ntiles * 16;
            for (int wc = 0; wc < nwc; wc++) {
                const int s = wc & 3;
                if (wc >= 4) { MBARRIER_WAIT_PARITY(WE(s), weph[s]); weph[s] ^= 1; }
                MBARRIER_EXPECT_TX(WF(s), 32768);
                BULK_G2S(sb + W_OFF + s * 32768, wsrc + (size_t)(wc & 15) * 32768, 32768, WF(s));
            }
        }
    } else {
        // ================= A loaders (448 thr) + epilogue (warps 2-9) =========
        const int lt = tid - 64;
        const bool is_epi = (wid <= 9);
        int arph[2] = {0, 0};
        int c = 0;

        for (int tt = 0; tt < ntiles; tt++) {
            const int tile = bid + GRID_GEMM * tt;
            const int m0   = tile * 128;

            #pragma unroll 1
            for (int kb = 0; kb < 4; kb++) {
                // epilogue of previous tile between kb1 and kb2 loads
                if (kb == 2 && tt > 0 && is_epi) {
                    const int ptile = bid + GRID_GEMM * (tt - 1);
                    MBARRIER_WAIT_PARITY(MDN, (tt - 1) & 1);
                    TCGEN05_FENCE_AFTER();
                    {
                        const int cg = (wid <= 5) ? 0 : 1;
                        const int m  = (wid & 3) * 32 + lid;
                        const int pn0 = (ptile * 128) & (N_ - 1);
                        const int pbb = (ptile * 128) >> 12;
                        float* __restrict__ orow = out + ((size_t)(pn0 + m) * B_ + pbb) * CH_;
                        const float* __restrict__ aw = g_attw + pbb * DW;
                        #pragma unroll 1
                        for (int cc = 0; cc < 4; cc++) {
                            uint32_t hr0[32], hr1[32];
                            TCGEN05_LD_X32(hr0, tmem + cg * 256 + cc * 32);
                            TCGEN05_LD_X32(hr1, tmem + cg * 256 + 128 + cc * 32);
                            TCGEN05_WAIT_LD();
                            #pragma unroll
                            for (int qq = 0; qq < 8; qq++) {
                                const int ch = cg * 128 + cc * 32 + qq * 4;
                                float4 b0 = *(const float4*)&b_conv[ch];
                                float4 b1 = *(const float4*)&b_conv[256 + ch];
                                float4 a0 = *(const float4*)&aw[ch];
                                float4 a1 = *(const float4*)&aw[256 + ch];
                                float4 o;
                                o.x = a0.x * fmaxf(__uint_as_float(hr0[qq*4+0]) + b0.x, 0.f)
                                    + a1.x * fmaxf(__uint_as_float(hr1[qq*4+0]) + b1.x, 0.f);
                                o.y = a0.y * fmaxf(__uint_as_float(hr0[qq*4+1]) + b0.y, 0.f)
                                    + a1.y * fmaxf(__uint_as_float(hr1[qq*4+1]) + b1.y, 0.f);
                                o.z = a0.z * fmaxf(__uint_as_float(hr0[qq*4+2]) + b0.z, 0.f)
                                    + a1.z * fmaxf(__uint_as_float(hr1[qq*4+2]) + b1.z, 0.f);
                                o.w = a0.w * fmaxf(__uint_as_float(hr0[qq*4+3]) + b0.w, 0.f)
                                    + a1.w * fmaxf(__uint_as_float(hr1[qq*4+3]) + b1.w, 0.f);
                                *(float4*)(orow + ch) = o;
                            }
                        }
                    }
                    MBARRIER_ARRIVE(EPI);
                }

                const int q = c & 1;
                if (c >= 2) { MBARRIER_WAIT_PARITY(AR(q), arph[q]); arph[q] ^= 1; }
                const uint32_t ab = sb + A_OFF + q * 32768;
                for (int f = lt; f < 2048; f += 448) {
                    const int r = f >> 4, qq = f & 15;
                    const float4 v = *(const float4*)&x[(size_t)(m0 + r) * 256 + kb * 64 + qq * 4];
                    uint32_t h01, h23, l01, l23;
                    split4(v, h01, h23, l01, l23);
                    const uint32_t off = (uint32_t)r * 128 + (((uint32_t)qq * 8) ^ ((uint32_t)(r & 7) << 4));
                    asm volatile("st.shared.v2.b32 [%0], {%1,%2};" :: "r"(ab + off), "r"(h01), "r"(h23) : "memory");
                    asm volatile("st.shared.v2.b32 [%0], {%1,%2};" :: "r"(ab + 16384 + off), "r"(l01), "r"(l23) : "memory");
                }
                asm volatile("fence.proxy.async.shared::cta;" ::: "memory");
                MBARRIER_ARRIVE(AF(q));
                c++;
            }
        }

        // final tile epilogue
        if (is_epi) {
            const int ltile = bid + GRID_GEMM * (ntiles - 1);
            MBARRIER_WAIT_PARITY(MDN, (ntiles - 1) & 1);
            TCGEN05_FENCE_AFTER();
            const int cg = (wid <= 5) ? 0 : 1;
            const int m  = (wid & 3) * 32 + lid;
            const int pn0 = (ltile * 128) & (N_ - 1);
            const int pbb = (ltile * 128) >> 12;
            float* __restrict__ orow = out + ((size_t)(pn0 + m) * B_ + pbb) * CH_;
            const float* __restrict__ aw = g_attw + pbb * DW;
            #pragma unroll 1
            for (int cc = 0; cc < 4; cc++) {
                uint32_t hr0[32], hr1[32];
                TCGEN05_LD_X32(hr0, tmem + cg * 256 + cc * 32);
                TCGEN05_LD_X32(hr1, tmem + cg * 256 + 128 + cc * 32);
                TCGEN05_WAIT_LD();
                #pragma unroll
                for (int qq = 0; qq < 8; qq++) {
                    const int ch = cg * 128 + cc * 32 + qq * 4;
                    float4 b0 = *(const float4*)&b_conv[ch];
                    float4 b1 = *(const float4*)&b_conv[256 + ch];
                    float4 a0 = *(const float4*)&aw[ch];
                    float4 a1 = *(const float4*)&aw[256 + ch];
                    float4 o;
                    o.x = a0.x * fmaxf(__uint_as_float(hr0[qq*4+0]) + b0.x, 0.f)
                        + a1.x * fmaxf(__uint_as_float(hr1[qq*4+0]) + b1.x, 0.f);
                    o.y = a0.y * fmaxf(__uint_as_float(hr0[qq*4+1]) + b0.y, 0.f)
                        + a1.y * fmaxf(__uint_as_float(hr1[qq*4+1]) + b1.y, 0.f);
                    o.z = a0.z * fmaxf(__uint_as_float(hr0[qq*4+2]) + b0.z, 0.f)
                        + a1.z * fmaxf(__uint_as_float(hr1[qq*4+2]) + b1.z, 0.f);
                    o.w = a0.w * fmaxf(__uint_as_float(hr0[qq*4+3]) + b0.w, 0.f)
                        + a1.w * fmaxf(__uint_as_float(hr1[qq*4+3]) + b1.w, 0.f);
                    *(float4*)(orow + ch) = o;
                }
            }
        }
    }

    __syncthreads();
    if (wid == 0) { TCGEN05_DEALLOC(tmem, 512); TCGEN05_RELINQ(); }

#else  // ------------------- fp32 FFMA fallback (plain sm_103) --------------
    float (*As)[64]  = (float(*)[64])smem;
    float (*Bs)[516] = (float(*)[516])(smem + 16 * 64 * 4);

    const int trow = tid >> 6;
    const int tcol = tid & 63;
    const int aM = tid >> 2, aK = (tid & 3) << 2;
    const int bD = tid >> 2, bK = (tid & 3) << 2;

    for (int tile = blockIdx.x; tile < NTILES_TOTAL; tile += gridDim.x) {
        const int m0 = tile * 128;
        const int bb = m0 >> 12;
        const int n0 = m0 & (N_ - 1);
        for (int sub = 0; sub < 2; sub++) {
            const int ms = m0 + sub * 64;
            float acc[8][8];
            #pragma unroll
            for (int i = 0; i < 8; i++)
                #pragma unroll
                for (int jj = 0; jj < 8; jj++) acc[i][jj] = 0.f;

            float4 aReg = make_float4(0.f, 0.f, 0.f, 0.f);
            float4 bReg[4];
            if (tid < 256)
                aReg = *(const float4*)&x[(size_t)(ms + aM) * CIN + aK];
            #pragma unroll
            for (int p = 0; p < 4; p++)
                bReg[p] = *(const float4*)&w_conv[(size_t)(bD + p * 128) * CIN + bK];

            for (int ks = 0; ks < CIN; ks += 16) {
                __syncthreads();
                if (tid < 256) {
                    As[aK + 0][aM] = aReg.x; As[aK + 1][aM] = aReg.y;
                    As[aK + 2][aM] = aReg.z; As[aK + 3][aM] = aReg.w;
                }
                #pragma unroll
                for (int p = 0; p < 4; p++) {
                    const int d = bD + p * 128;
                    Bs[bK + 0][d] = bReg[p].x; Bs[bK + 1][d] = bReg[p].y;
                    Bs[bK + 2][d] = bReg[p].z; Bs[bK + 3][d] = bReg[p].w;
                }
                __syncthreads();
                if (ks + 16 < CIN) {
                    const int kn = ks + 16;
                    if (tid < 256)
                        aReg = *(const float4*)&x[(size_t)(ms + aM) * CIN + kn + aK];
                    #pragma unroll
                    for (int p = 0; p < 4; p++)
                        bReg[p] = *(const float4*)&w_conv[(size_t)(bD + p * 128) * CIN + kn + bK];
                }
                #pragma unroll
                for (int k = 0; k < 16; k++) {
                    float a[8], bf[8];
                    *(float4*)&a[0]  = *(const float4*)&As[k][trow * 8];
                    *(float4*)&a[4]  = *(const float4*)&As[k][trow * 8 + 4];
                    *(float4*)&bf[0] = *(const float4*)&Bs[k][tcol * 4];
                    *(float4*)&bf[4] = *(const float4*)&Bs[k][tcol * 4 + 256];
                    #pragma unroll
                    for (int i = 0; i < 8; i++)
                        #pragma unroll
                        for (int jj = 0; jj < 8; jj++)
                            acc[i][jj] += a[i] * bf[jj];
                }
            }
            __syncthreads();

            const int cbase = tcol * 4;
            float a0[4], a1[4], bias0[4], bias1[4];
            #pragma unroll
            for (int jj = 0; jj < 4; jj++) {
                a0[jj]    = g_attw[bb * DW + cbase + jj];
                a1[jj]    = g_attw[bb * DW + 256 + cbase + jj];
                bias0[jj] = b_conv[cbase + jj];
                bias1[jj] = b_conv[256 + cbase + jj];
            }
            #pragma unroll
            for (int i = 0; i < 8; i++) {
                const int n = n0 + sub * 64 + trow * 8 + i;
                float4 o;
                o.x = a0[0] * fmaxf(acc[i][0] + bias0[0], 0.f) + a1[0] * fmaxf(acc[i][4] + bias1[0], 0.f);
                o.y = a0[1] * fmaxf(acc[i][1] + bias0[1], 0.f) + a1[1] * fmaxf(acc[i][5] + bias1[1], 0.f);
                o.z = a0[2] * fmaxf(acc[i][2] + bias0[2], 0.f) + a1[2] * fmaxf(acc[i][6] + bias1[2], 0.f);
                o.w = a0[3] * fmaxf(acc[i][3] + bias0[3], 0.f) + a1[3] * fmaxf(acc[i][7] + bias1[3], 0.f);
                *(float4*)&out[((size_t)n * B_ + bb) * CH_ + cbase] = o;
            }
        }
    }
#endif
}

extern "C" void kernel_launch(void* const* d_in, const int* in_sizes, int n_in,
                              void* d_out, int out_size) {
    const float* x      = (const float*)d_in[0];
    const float* w_conv = (const float*)d_in[1];
    const float* b_conv = (const float*)d_in[2];
    const float* w_fc1  = (const float*)d_in[3];
    const float* b_fc1  = (const float*)d_in[4];
    const float* w_fc2  = (const float*)d_in[5];
    // d_in[6] = b_fc2: cancels in the softmax-pair difference, unused.
    float* out = (float*)d_out;

    cudaFuncSetAttribute(gemm_kernel, cudaFuncAttributeMaxDynamicSharedMemorySize, SMEM_TOTAL);

    setup1_kernel<<<128, 512>>>(x, w_conv, b_conv);
    setup2_kernel<<<B_, 256>>>(w_fc1, b_fc1, w_fc2);
    gemm_kernel<<<GRID_GEMM, 512, SMEM_TOTAL>>>(x, w_conv, b_conv, out);
}

// round 8
// speedup vs baseline: 1.2073x; 1.0981x over previous
#include <cuda_runtime.h>
#include <cuda_bf16.h>
#include <cstdint>
#include <math.h>

#define B_    16
#define N_    4096
#define CIN   256
#define CH_   256
#define DW    512
#define IN_   128
#define NTILES_TOTAL 512   // 65536 rows / 128

// tcgen05 asm only compiles under an 'a'-suffixed target pass.
#if defined(__CUDA_ARCH_FEAT_SM103_ALL) || defined(__CUDA_ARCH_FEAT_SM100_ALL) || defined(__CUDA_ARCH_FEAT_SM101_ALL)
#define USE_TCGEN05 1
#else
#define USE_TCGEN05 0
#endif

// -------------------- device scratch --------------------
__device__ float g_attw[B_ * DW];
__device__ float g_h[B_ * 2 * DW];
// 16 pre-swizzled W chunk images of 32KB each (256 rows x 128B, SW128 baked in).
// chunk j = kb*4 + islo*2 + nh.
// Row perm: w_conv row d (c=d&255, r=d>>8) -> nh=c>>7, local row=(c&127)+r*128.
// D col = nh*256 + (c&127) + r*128.
__device__ __nv_bfloat16 g_w3[16 * 256 * 64];

// -------------------- PTX helpers --------------------
__device__ __forceinline__ uint32_t smem_u32(const void* p) {
    uint32_t a;
    asm("{ .reg .u64 t; cvta.to.shared.u64 t, %1; cvt.u32.u64 %0, t; }" : "=r"(a) : "l"(p));
    return a;
}
__device__ __forceinline__ uint32_t elect_one() {
    uint32_t pred;
    asm volatile("{\n\t.reg .pred p;\n\telect.sync _|p, 0xFFFFFFFF;\n\tselp.b32 %0, 1, 0, p;\n\t}" : "=r"(pred));
    return pred;
}
#define TCGEN05_ALLOC(sa, n) \
    asm volatile("tcgen05.alloc.cta_group::1.sync.aligned.shared::cta.b32 [%0], %1;" :: "r"((uint32_t)(sa)), "r"((uint32_t)(n)) : "memory")
#define TCGEN05_DEALLOC(t, n) \
    asm volatile("tcgen05.dealloc.cta_group::1.sync.aligned.b32 %0, %1;" :: "r"(t), "r"((uint32_t)(n)))
#define TCGEN05_RELINQ() \
    asm volatile("tcgen05.relinquish_alloc_permit.cta_group::1.sync.aligned;")
#define TCGEN05_COMMIT(mb) \
    asm volatile("tcgen05.commit.cta_group::1.mbarrier::arrive::one.shared::cluster.b64 [%0];" :: "r"((uint32_t)(mb)) : "memory")
#define TCGEN05_WAIT_LD() asm volatile("tcgen05.wait::ld.sync.aligned;" ::: "memory")
#define TCGEN05_FENCE_AFTER() asm volatile("tcgen05.fence::after_thread_sync;" ::: "memory")
#define MBARRIER_INIT(mb, cnt) \
    asm volatile("mbarrier.init.shared.b64 [%0], %1;" :: "r"((uint32_t)(mb)), "r"((uint32_t)(cnt)) : "memory")
#define MBARRIER_ARRIVE(mb) \
    asm volatile("mbarrier.arrive.shared.b64 _, [%0];" :: "r"((uint32_t)(mb)) : "memory")
#define MBARRIER_EXPECT_TX(mb, bytes) \
    asm volatile("mbarrier.arrive.expect_tx.shared.b64 _, [%0], %1;" :: "r"((uint32_t)(mb)), "r"((uint32_t)(bytes)) : "memory")
#define MBARRIER_WAIT_PARITY(mb, ph) do { \
    uint32_t _m = (uint32_t)(mb), _p = (uint32_t)(ph), _d; \
    asm volatile("{\n\t.reg .pred p;\n\tmbarrier.try_wait.parity.acquire.cta.shared::cta.b64 p, [%1], %2;\n\tselp.b32 %0, 1, 0, p;\n\t}" \
        : "=r"(_d) : "r"(_m), "r"(_p) : "memory"); \
    if (!_d) { \
        asm volatile("{\n\t.reg .pred P1;\n\tWL_%=:\n\tmbarrier.try_wait.parity.acquire.cta.shared::cta.b64 P1, [%0], %1, 0x989680;\n\t@P1 bra.uni WD_%=;\n\tbra.uni WL_%=;\n\tWD_%=:\n\t}" \
            :: "r"(_m), "r"(_p) : "memory"); \
    } \
} while (0)
#define BULK_G2S(dst, src, bytes, mb) \
    asm volatile("cp.async.bulk.shared::cta.global.mbarrier::complete_tx::bytes [%0], [%1], %2, [%3];" \
        :: "r"((uint32_t)(dst)), "l"(src), "r"((uint32_t)(bytes)), "r"((uint32_t)(mb)) : "memory")
#define TCGEN05_LD_X32(r, ta) \
    asm volatile("tcgen05.ld.sync.aligned.32x32b.x32.b32 " \
        "{%0,%1,%2,%3,%4,%5,%6,%7,%8,%9,%10,%11,%12,%13,%14,%15," \
        "%16,%17,%18,%19,%20,%21,%22,%23,%24,%25,%26,%27,%28,%29,%30,%31}, [%32];" \
        : "=r"((r)[0]),"=r"((r)[1]),"=r"((r)[2]),"=r"((r)[3]),"=r"((r)[4]),"=r"((r)[5]),"=r"((r)[6]),"=r"((r)[7]), \
          "=r"((r)[8]),"=r"((r)[9]),"=r"((r)[10]),"=r"((r)[11]),"=r"((r)[12]),"=r"((r)[13]),"=r"((r)[14]),"=r"((r)[15]), \
          "=r"((r)[16]),"=r"((r)[17]),"=r"((r)[18]),"=r"((r)[19]),"=r"((r)[20]),"=r"((r)[21]),"=r"((r)[22]),"=r"((r)[23]), \
          "=r"((r)[24]),"=r"((r)[25]),"=r"((r)[26]),"=r"((r)[27]),"=r"((r)[28]),"=r"((r)[29]),"=r"((r)[30]),"=r"((r)[31]) \
        : "r"(ta))

static constexpr uint64_t SMEM_DESC_BASE_SW128 =
    (uint64_t(2) << 61) | (uint64_t(1) << 46) | (uint64_t(64) << 32) | (uint64_t(1) << 16);
#define MAKE_SMEM_DESC(a) (SMEM_DESC_BASE_SW128 | ((uint64_t)((a) >> 4) & 0x3FFF))

#if USE_TCGEN05
// SS-mode cg1 bf16 MMA: D[128,256] += A[128,16] * B[256,16]^T
__device__ __forceinline__ void mma_f16_ss(uint32_t d, uint64_t ad, uint64_t bd, uint32_t idesc, bool acc) {
    uint32_t en = acc ? 1u : 0u;
    asm volatile(
        "{\n\t.reg .pred p;\n\tsetp.ne.u32 p, %5, 0;\n\t"
        "tcgen05.mma.cta_group::1.kind::f16 [%0], %1, %2, %3, {%4, %4, %4, %4}, p;\n\t}"
        :: "r"(d), "l"(ad), "l"(bd), "r"(idesc), "r"(0u), "r"(en) : "memory");
}
#endif
// idesc: F32 accum, BF16 x BF16, M=128, N=256
static constexpr uint32_t IDESC =
    (1u << 4) | (1u << 7) | (1u << 10) | ((256u / 8u) << 17) | ((128u / 16u) << 24);

// fp32 -> bf16 hi/lo split, packed pairs
__device__ __forceinline__ void split4(const float4 v, uint32_t& h01, uint32_t& h23,
                                       uint32_t& l01, uint32_t& l23) {
    __nv_bfloat162 h0 = __floats2bfloat162_rn(v.x, v.y);
    __nv_bfloat162 h1 = __floats2bfloat162_rn(v.z, v.w);
    __nv_bfloat162 l0 = __floats2bfloat162_rn(v.x - __bfloat162float(h0.x),
                                              v.y - __bfloat162float(h0.y));
    __nv_bfloat162 l1 = __floats2bfloat162_rn(v.z - __bfloat162float(h1.x),
                                              v.w - __bfloat162float(h1.y));
    h01 = *(uint32_t*)&h0; h23 = *(uint32_t*)&h1;
    l01 = *(uint32_t*)&l0; l23 = *(uint32_t*)&l1;
}

// ---------------------------------------------------------------------------
// Setup 1: blocks 0..127 = conv rows (K-split-4); blocks 128..191 = prep_w.
// ---------------------------------------------------------------------------
__global__ __launch_bounds__(512) void setup1_kernel(
    const float* __restrict__ x,
    const float* __restrict__ w_conv,
    const float* __restrict__ b_conv)
{
    const int tid = threadIdx.x;

    if (blockIdx.x >= 128) {
        // ---- prep_w: 64 blocks x 512 threads x 4 floats ----
        const int gi = ((blockIdx.x - 128) * 512 + tid) * 4;
        float4 v = *(const float4*)(w_conv + gi);
        const int d = gi >> 8, k = gi & 255;
        uint32_t h01, h23, l01, l23;
        split4(v, h01, h23, l01, l23);
        const int c = d & 255, r = d >> 8;
        const int nh = c >> 7;
        const int lrow = (c & 127) + (r << 7);
        const int kb = k >> 6, kc = k & 63;
        const uint32_t off = (uint32_t)lrow * 128 + (((uint32_t)kc * 2) ^ ((uint32_t)(lrow & 7) << 4));
        char* basehi = (char*)g_w3 + (size_t)(kb * 4 + nh) * 32768 + off;
        char* baselo = (char*)g_w3 + (size_t)(kb * 4 + 2 + nh) * 32768 + off;
        *(uint2*)basehi = make_uint2(h01, h23);
        *(uint2*)baselo = make_uint2(l01, l23);
        return;
    }

    // ---- conv rows: blk = (b<<3) | (rowsel<<2) | dq ----
    const int b      = blockIdx.x >> 3;
    const int rowsel = (blockIdx.x >> 2) & 1;
    const int dq     = blockIdx.x & 3;
    const int row    = rowsel * 1024;

    __shared__ float xs[CIN];
    __shared__ float psum[512];
    if (tid < CIN) xs[tid] = x[((size_t)b * N_ + row) * CIN + tid];
    __syncthreads();

    const int dl = tid >> 2;        // 0..127
    const int kq = tid & 3;         // K quarter
    const int d  = dq * 128 + dl;
    const float4* w  = (const float4*)(w_conv + d * CIN + kq * 64);
    const float4* xv = (const float4*)(xs + kq * 64);
    float s = 0.f;
    #pragma unroll
    for (int k4 = 0; k4 < 16; k4++) {
        float4 wv = w[k4];
        float4 x4 = xv[k4];
        s += wv.x * x4.x + wv.y * x4.y + wv.z * x4.z + wv.w * x4.w;
    }
    psum[tid] = s;
    __syncthreads();
    if (kq == 0) {
        float t = psum[tid] + psum[tid + 1] + psum[tid + 2] + psum[tid + 3];
        g_h[(b * 2 + rowsel) * DW + d] = fmaxf(t + b_conv[d], 0.f);
    }
}

// ---------------------------------------------------------------------------
// Setup 2: fc chain per batch; attw = sigmoid(pair difference), b_fc2 cancels.
// ---------------------------------------------------------------------------
__global__ __launch_bounds__(256) void setup2_kernel(
    const float* __restrict__ w_fc1,
    const float* __restrict__ b_fc1,
    const float* __restrict__ w_fc2)
{
    const int b   = blockIdx.x;
    const int tid = threadIdx.x;
    __shared__ float gap0[CH_], gap1[CH_];
    __shared__ float g0[IN_], g1[IN_], gd[IN_];

    const float* h0 = g_h + (b * 2 + 0) * DW;
    const float* h1 = g_h + (b * 2 + 1) * DW;
    gap0[tid] = h0[tid] + h0[tid + CH_];
    gap1[tid] = h1[tid] + h1[tid + CH_];
    __syncthreads();

    {
        const int i = tid & 127;
        const float* gp = (tid < 128) ? gap0 : gap1;
        const float4* w = (const float4*)(w_fc1 + i * CH_);
        float s = 0.f;
        #pragma unroll 8
        for (int k4 = 0; k4 < CH_ / 4; k4++) {
            float4 wv = w[k4];
            float4 gv = ((const float4*)gp)[k4];
            s += wv.x * gv.x + wv.y * gv.y + wv.z * gv.z + wv.w * gv.w;
        }
        s = fmaxf(s + b_fc1[i], 0.f);
        if (tid < 128) g0[i] = s; else g1[i] = s;
    }
    __syncthreads();
    if (tid < IN_) gd[tid] = g0[tid] - g1[tid];
    __syncthreads();

    #pragma unroll
    for (int dd = 0; dd < 2; dd++) {
        const int d = tid + dd * 256;
        const float4* w = (const float4*)(w_fc2 + d * IN_);
        float s = 0.f;
        #pragma unroll 8
        for (int k4 = 0; k4 < IN_ / 4; k4++) {
            float4 wv = w[k4];
            float4 gv = ((const float4*)gd)[k4];
            s += wv.x * gv.x + wv.y * gv.y + wv.z * gv.z + wv.w * gv.w;
        }
        g_attw[b * DW + d] = 1.f / (1.f + expf(-s));
    }
}

// ---------------------------------------------------------------------------
// GEMM: persistent cg1 tcgen05 with HALF-TILE TMEM PING-PONG.
// Per 128-row tile: two N=256 halves (h = channel group). TMEM cols
// [h*256, h*256+256) accumulate half h; MMA of half h+1 overlaps epilogue
// of half h. A = 4 resident 32KB stages per tile (loaded once, used by both
// halves, freed per-kb). W = 3-stage 32KB ring, 16 chunks/tile.
// Warp 0 = MMA, warp 1 = W producer, warps 2-9 = epilogue, 10-15 = A loaders.
// ---------------------------------------------------------------------------
#define A_OFF   1024
#define W_OFF   (1024 + 4 * 32768)
#define SMEM_TOTAL (1024 + 4 * 32768 + 3 * 32768)
#define GRID_GEMM 148

__global__ __launch_bounds__(512, 1)
void gemm_kernel(const float* __restrict__ x,
                 const float* __restrict__ w_conv,
                 const float* __restrict__ b_conv,
                 float* __restrict__ out)
{
    extern __shared__ __align__(1024) char smem[];
    const int tid = threadIdx.x;

#if USE_TCGEN05
    const uint32_t sb = smem_u32(smem);
    const int wid = tid >> 5, lid = tid & 31;
    const int bid = blockIdx.x;
    const int ntiles = (NTILES_TOTAL - bid + GRID_GEMM - 1) / GRID_GEMM;

    #define WF(s)   (sb + 8   + (s) * 8)
    #define WE(s)   (sb + 32  + (s) * 8)
    #define AF(k)   (sb + 56  + (k) * 8)
    #define AR(k)   (sb + 88  + (k) * 8)
    #define MDN(h)  (sb + 120 + (h) * 8)
    #define EPIF(h) (sb + 136 + (h) * 8)

    if (wid == 0) TCGEN05_ALLOC(sb, 512);
    if (tid == 0) {
        #pragma unroll
        for (int s = 0; s < 3; s++) { MBARRIER_INIT(WF(s), 1); MBARRIER_INIT(WE(s), 1); }
        #pragma unroll
        for (int k = 0; k < 4; k++) { MBARRIER_INIT(AF(k), 192); MBARRIER_INIT(AR(k), 1); }
        MBARRIER_INIT(MDN(0), 1);  MBARRIER_INIT(MDN(1), 1);
        MBARRIER_INIT(EPIF(0), 256); MBARRIER_INIT(EPIF(1), 256);
    }
    __syncthreads();
    uint32_t tmem;
    asm volatile("ld.shared.b32 %0, [%1];" : "=r"(tmem) : "r"(sb));

    if (wid == 0) {
        // ================= MMA warp =================
        if (elect_one()) {
            int wstage = 0;
            int wfph[3] = {0, 0, 0};
            for (int tt = 0; tt < ntiles; tt++) {
                const int tpar = tt & 1;
                #pragma unroll 1
                for (int h = 0; h < 2; h++) {
                    if (tt > 0) MBARRIER_WAIT_PARITY(EPIF(h), (tt - 1) & 1);
                    const uint32_t dst = tmem + h * 256;
                    #pragma unroll 1
                    for (int kb = 0; kb < 4; kb++) {
                        MBARRIER_WAIT_PARITY(AF(kb), tpar);
                        const uint32_t ab = sb + A_OFF + kb * 32768;
                        const uint64_t ahi = MAKE_SMEM_DESC(ab);
                        const uint64_t alo = MAKE_SMEM_DESC(ab + 16384);
                        // --- whi chunk: ahi*whi + alo*whi ---
                        MBARRIER_WAIT_PARITY(WF(wstage), wfph[wstage]); wfph[wstage] ^= 1;
                        {
                            const uint64_t wd = MAKE_SMEM_DESC(sb + W_OFF + wstage * 32768);
                            #pragma unroll
                            for (int k = 0; k < 4; k++)
                                mma_f16_ss(dst, ahi + k * 2, wd + k * 2, IDESC, !(kb == 0 && k == 0));
                            #pragma unroll
                            for (int k = 0; k < 4; k++)
                                mma_f16_ss(dst, alo + k * 2, wd + k * 2, IDESC, true);
                            TCGEN05_COMMIT(WE(wstage));
                        }
                        wstage = (wstage == 2) ? 0 : wstage + 1;
                        // --- wlo chunk: ahi*wlo ---
                        MBARRIER_WAIT_PARITY(WF(wstage), wfph[wstage]); wfph[wstage] ^= 1;
                        {
                            const uint64_t wd = MAKE_SMEM_DESC(sb + W_OFF + wstage * 32768);
                            #pragma unroll
                            for (int k = 0; k < 4; k++)
                                mma_f16_ss(dst, ahi + k * 2, wd + k * 2, IDESC, true);
                            TCGEN05_COMMIT(WE(wstage));
                        }
                        wstage = (wstage == 2) ? 0 : wstage + 1;
                        if (h == 1) TCGEN05_COMMIT(AR(kb));   // A stage kb free
                    }
                    TCGEN05_COMMIT(MDN(h));                    // half h ready
                }
            }
        }
    } else if (wid == 1) {
        // ================= W producer: continuous 3-stage ring ==============
        if (elect_one()) {
            const char* wsrc = (const char*)g_w3;
            int wstage = 0, wc = 0;
            int weph[3] = {0, 0, 0};
            for (int tt = 0; tt < ntiles; tt++)
                #pragma unroll 1
                for (int h = 0; h < 2; h++)
                    #pragma unroll 1
                    for (int kb = 0; kb < 4; kb++)
                        #pragma unroll
                        for (int isl = 0; isl < 2; isl++) {
                            if (wc >= 3) { MBARRIER_WAIT_PARITY(WE(wstage), weph[wstage]); weph[wstage] ^= 1; }
                            MBARRIER_EXPECT_TX(WF(wstage), 32768);
                            BULK_G2S(sb + W_OFF + wstage * 32768,
                                     wsrc + (size_t)(kb * 4 + isl * 2 + h) * 32768,
                                     32768, WF(wstage));
                            wstage = (wstage == 2) ? 0 : wstage + 1;
                            wc++;
                        }
        }
    } else if (wid <= 9) {
        // ================= Epilogue warps (8 warps, 256 threads) ============
        const int cg = (wid <= 5) ? 0 : 1;       // 64-channel sub-group
        const int m  = (wid & 3) * 32 + lid;     // row via own subpartition
        for (int tt = 0; tt < ntiles; tt++) {
            const int m0 = (bid + GRID_GEMM * tt) * 128;
            const int bb = m0 >> 12;
            const int n  = (m0 & (N_ - 1)) + m;
            float* __restrict__ orow = out + ((size_t)n * B_ + bb) * CH_;
            const float* __restrict__ aw = g_attw + bb * DW;
            #pragma unroll 1
            for (int h = 0; h < 2; h++) {
                MBARRIER_WAIT_PARITY(MDN(h), tt & 1);
                TCGEN05_FENCE_AFTER();
                #pragma unroll
                for (int cc = 0; cc < 2; cc++) {
                    uint32_t hr0[32], hr1[32];
                    TCGEN05_LD_X32(hr0, tmem + h * 256 + cg * 64 + cc * 32);        // radix 0
                    TCGEN05_LD_X32(hr1, tmem + h * 256 + 128 + cg * 64 + cc * 32);  // radix 1
                    TCGEN05_WAIT_LD();
                    #pragma unroll
                    for (int qq = 0; qq < 8; qq++) {
                        const int ch = h * 128 + cg * 64 + cc * 32 + qq * 4;
                        float4 b0 = *(const float4*)&b_conv[ch];
                        float4 b1 = *(const float4*)&b_conv[256 + ch];
                        float4 a0 = *(const float4*)&aw[ch];
                        float4 a1 = *(const float4*)&aw[256 + ch];
                        float4 o;
                        o.x = a0.x * fmaxf(__uint_as_float(hr0[qq*4+0]) + b0.x, 0.f)
                            + a1.x * fmaxf(__uint_as_float(hr1[qq*4+0]) + b1.x, 0.f);
                        o.y = a0.y * fmaxf(__uint_as_float(hr0[qq*4+1]) + b0.y, 0.f)
                            + a1.y * fmaxf(__uint_as_float(hr1[qq*4+1]) + b1.y, 0.f);
                        o.z = a0.z * fmaxf(__uint_as_float(hr0[qq*4+2]) + b0.z, 0.f)
                            + a1.z * fmaxf(__uint_as_float(hr1[qq*4+2]) + b1.z, 0.f);
                        o.w = a0.w * fmaxf(__uint_as_float(hr0[qq*4+3]) + b0.w, 0.f)
                            + a1.w * fmaxf(__uint_as_float(hr1[qq*4+3]) + b1.w, 0.f);
                        *(float4*)(orow + ch) = o;
                    }
                }
                MBARRIER_ARRIVE(EPIF(h));   // TMEM half h free
            }
        }
    } else {
        // ================= A loaders (6 warps, 192 threads) =================
        const int lt = tid - 320;
        for (int tt = 0; tt < ntiles; tt++) {
            const int m0 = (bid + GRID_GEMM * tt) * 128;
            #pragma unroll 1
            for (int kb = 0; kb < 4; kb++) {
                if (tt > 0) MBARRIER_WAIT_PARITY(AR(kb), (tt - 1) & 1);
                const uint32_t ab = sb + A_OFF + kb * 32768;
                for (int f = lt; f < 2048; f += 192) {
                    const int r = f >> 4, qq = f & 15;
                    const float4 v = *(const float4*)&x[(size_t)(m0 + r) * 256 + kb * 64 + qq * 4];
                    uint32_t h01, h23, l01, l23;
                    split4(v, h01, h23, l01, l23);
                    const uint32_t off = (uint32_t)r * 128 + (((uint32_t)qq * 8) ^ ((uint32_t)(r & 7) << 4));
                    asm volatile("st.shared.v2.b32 [%0], {%1,%2};" :: "r"(ab + off), "r"(h01), "r"(h23) : "memory");
                    asm volatile("st.shared.v2.b32 [%0], {%1,%2};" :: "r"(ab + 16384 + off), "r"(l01), "r"(l23) : "memory");
                }
                asm volatile("fence.proxy.async.shared::cta;" ::: "memory");
                MBARRIER_ARRIVE(AF(kb));
            }
        }
    }

    __syncthreads();
    if (wid == 0) { TCGEN05_DEALLOC(tmem, 512); TCGEN05_RELINQ(); }

#else  // ------------------- fp32 FFMA fallback (plain sm_103) --------------
    float (*As)[64]  = (float(*)[64])smem;
    float (*Bs)[516] = (float(*)[516])(smem + 16 * 64 * 4);

    const int trow = tid >> 6;
    const int tcol = tid & 63;
    const int aM = tid >> 2, aK = (tid & 3) << 2;
    const int bD = tid >> 2, bK = (tid & 3) << 2;

    for (int tile = blockIdx.x; tile < NTILES_TOTAL; tile += gridDim.x) {
        const int m0 = tile * 128;
        const int bb = m0 >> 12;
        const int n0 = m0 & (N_ - 1);
        for (int sub = 0; sub < 2; sub++) {
            const int ms = m0 + sub * 64;
            float acc[8][8];
            #pragma unroll
            for (int i = 0; i < 8; i++)
                #pragma unroll
                for (int jj = 0; jj < 8; jj++) acc[i][jj] = 0.f;

            float4 aReg = make_float4(0.f, 0.f, 0.f, 0.f);
            float4 bReg[4];
            if (tid < 256)
                aReg = *(const float4*)&x[(size_t)(ms + aM) * CIN + aK];
            #pragma unroll
            for (int p = 0; p < 4; p++)
                bReg[p] = *(const float4*)&w_conv[(size_t)(bD + p * 128) * CIN + bK];

            for (int ks = 0; ks < CIN; ks += 16) {
                __syncthreads();
                if (tid < 256) {
                    As[aK + 0][aM] = aReg.x; As[aK + 1][aM] = aReg.y;
                    As[aK + 2][aM] = aReg.z; As[aK + 3][aM] = aReg.w;
                }
                #pragma unroll
                for (int p = 0; p < 4; p++) {
                    const int d = bD + p * 128;
                    Bs[bK + 0][d] = bReg[p].x; Bs[bK + 1][d] = bReg[p].y;
                    Bs[bK + 2][d] = bReg[p].z; Bs[bK + 3][d] = bReg[p].w;
                }
                __syncthreads();
                if (ks + 16 < CIN) {
                    const int kn = ks + 16;
                    if (tid < 256)
                        aReg = *(const float4*)&x[(size_t)(ms + aM) * CIN + kn + aK];
                    #pragma unroll
                    for (int p = 0; p < 4; p++)
                        bReg[p] = *(const float4*)&w_conv[(size_t)(bD + p * 128) * CIN + kn + bK];
                }
                #pragma unroll
                for (int k = 0; k < 16; k++) {
                    float a[8], bf[8];
                    *(float4*)&a[0]  = *(const float4*)&As[k][trow * 8];
                    *(float4*)&a[4]  = *(const float4*)&As[k][trow * 8 + 4];
                    *(float4*)&bf[0] = *(const float4*)&Bs[k][tcol * 4];
                    *(float4*)&bf[4] = *(const float4*)&Bs[k][tcol * 4 + 256];
                    #pragma unroll
                    for (int i = 0; i < 8; i++)
                        #pragma unroll
                        for (int jj = 0; jj < 8; jj++)
                            acc[i][jj] += a[i] * bf[jj];
                }
            }
            __syncthreads();

            const int cbase = tcol * 4;
            float a0[4], a1[4], bias0[4], bias1[4];
            #pragma unroll
            for (int jj = 0; jj < 4; jj++) {
                a0[jj]    = g_attw[bb * DW + cbase + jj];
                a1[jj]    = g_attw[bb * DW + 256 + cbase + jj];
                bias0[jj] = b_conv[cbase + jj];
                bias1[jj] = b_conv[256 + cbase + jj];
            }
            #pragma unroll
            for (int i = 0; i < 8; i++) {
                const int n = n0 + sub * 64 + trow * 8 + i;
                float4 o;
                o.x = a0[0] * fmaxf(acc[i][0] + bias0[0], 0.f) + a1[0] * fmaxf(acc[i][4] + bias1[0], 0.f);
                o.y = a0[1] * fmaxf(acc[i][1] + bias0[1], 0.f) + a1[1] * fmaxf(acc[i][5] + bias1[1], 0.f);
                o.z = a0[2] * fmaxf(acc[i][2] + bias0[2], 0.f) + a1[2] * fmaxf(acc[i][6] + bias1[2], 0.f);
                o.w = a0[3] * fmaxf(acc[i][3] + bias0[3], 0.f) + a1[3] * fmaxf(acc[i][7] + bias1[3], 0.f);
                *(float4*)&out[((size_t)n * B_ + bb) * CH_ + cbase] = o;
            }
        }
    }
#endif
}

extern "C" void kernel_launch(void* const* d_in, const int* in_sizes, int n_in,
                              void* d_out, int out_size) {
    const float* x      = (const float*)d_in[0];
    const float* w_conv = (const float*)d_in[1];
    const float* b_conv = (const float*)d_in[2];
    const float* w_fc1  = (const float*)d_in[3];
    const float* b_fc1  = (const float*)d_in[4];
    const float* w_fc2  = (const float*)d_in[5];
    // d_in[6] = b_fc2: cancels in the softmax-pair difference, unused.
    float* out = (float*)d_out;

    cudaFuncSetAttribute(gemm_kernel, cudaFuncAttributeMaxDynamicSharedMemorySize, SMEM_TOTAL);

    setup1_kernel<<<192, 512>>>(x, w_conv, b_conv);
    setup2_kernel<<<B_, 256>>>(w_fc1, b_fc1, w_fc2);
    gemm_kernel<<<GRID_GEMM, 512, SMEM_TOTAL>>>(x, w_conv, b_conv, out);
}